// round 1
// baseline (speedup 1.0000x reference)
#include <cuda_runtime.h>

#define V  100000
#define H  300
#define LL 64
#define B  64
#define G3 900

// ---------------- device state ----------------
__device__ float d_h0[B * H];
__device__ float d_h1[B * H];
__device__ float d_gi[B * G3];
__device__ float d_gh[B * G3];
__device__ int   d_ids[B];
__device__ unsigned long long d_amax[B];

__device__ __forceinline__ float* hbuf(int p) { return p ? d_h1 : d_h0; }

// ---------------- init ----------------
__global__ void init_kernel() {
    int i = blockIdx.x * blockDim.x + threadIdx.x;
    if (i < B * H) d_h0[i] = 0.f;
    if (i < B) { d_ids[i] = 0; d_amax[i] = 0ULL; }
}

// ---------------- GRU pre-activation GEMM ----------------
// z=0: gi[b][n] = sum_k x[b][k] * W_ih[n][k],  x = (relu?)(emb[id_b])
// z=1: gh[b][n] = sum_k h[b][k] * W_hh[n][k]
// BM=64, BN=16, BK=32
__global__ void gru_gemm(const float* __restrict__ emb,
                         const int*   __restrict__ ids,   // null -> use d_ids
                         int relu,
                         const float* __restrict__ Wih,
                         const float* __restrict__ Whh,
                         int p)                            // h parity (input buffer)
{
    __shared__ float As[32][65];
    __shared__ float Ws[32][17];
    __shared__ int   ids_s[B];

    const int z = blockIdx.z;
    const float* Wm  = z ? Whh : Wih;
    float*       out = z ? d_gh : d_gi;
    const float* h_in = hbuf(p);
    const int n0  = blockIdx.x * 16;
    const int tid = threadIdx.x;

    if (z == 0) {
        const int* idp = ids ? ids : d_ids;
        if (tid < B) ids_s[tid] = idp[tid];
    }
    __syncthreads();

    float acc[4] = {0.f, 0.f, 0.f, 0.f};
    const int tx = tid & 3;        // n fragment (4 cols)
    const int ty = tid >> 2;       // b (0..63)

    for (int k0 = 0; k0 < H; k0 += 32) {
        // A tile: 64 x 32
        #pragma unroll
        for (int i = 0; i < 8; i++) {
            int idx = tid + i * 256;
            int b = idx >> 5, kk = idx & 31;
            int k = k0 + kk;
            float v = 0.f;
            if (k < H) {
                if (z == 0) {
                    v = emb[ids_s[b] * H + k];
                    if (relu) v = fmaxf(v, 0.f);
                } else {
                    v = h_in[b * H + k];
                }
            }
            As[kk][b] = v;
        }
        // W tile: 16 x 32
        #pragma unroll
        for (int i = 0; i < 2; i++) {
            int idx = tid + i * 256;
            int n = idx >> 5, kk = idx & 31;
            int gn = n0 + n, k = k0 + kk;
            Ws[kk][n] = (gn < G3 && k < H) ? Wm[gn * H + k] : 0.f;
        }
        __syncthreads();
        #pragma unroll
        for (int kk = 0; kk < 32; kk++) {
            float a = As[kk][ty];
            #pragma unroll
            for (int j = 0; j < 4; j++)
                acc[j] += a * Ws[kk][tx * 4 + j];
        }
        __syncthreads();
    }
    #pragma unroll
    for (int j = 0; j < 4; j++) {
        int gn = n0 + tx * 4 + j;
        if (gn < G3) out[ty * G3 + gn] = acc[j];
    }
}

// ---------------- GRU elementwise combine ----------------
__global__ void gru_combine(const float* __restrict__ b_ih,
                            const float* __restrict__ b_hh,
                            int p)   // input parity; output to p^1
{
    int i = blockIdx.x * 256 + threadIdx.x;
    if (i >= B * H) return;
    const float* h_in  = hbuf(p);
    float*       h_out = hbuf(p ^ 1);
    int b = i / H, k = i % H;
    const float* gi = d_gi + b * G3;
    const float* gh = d_gh + b * G3;

    float sr = gi[k]         + b_ih[k]         + gh[k]         + b_hh[k];
    float sz = gi[H + k]     + b_ih[H + k]     + gh[H + k]     + b_hh[H + k];
    float in_ = gi[2 * H + k] + b_ih[2 * H + k];
    float hn  = gh[2 * H + k] + b_hh[2 * H + k];

    float r = 1.f / (1.f + expf(-sr));
    float z = 1.f / (1.f + expf(-sz));
    float n = tanhf(in_ + r * hn);
    h_out[i] = (1.f - z) * n + z * h_in[i];
}

// ---------------- logits GEMM + argmax ----------------
// C[b][v] = h[b,:] . out_W[v,:] + out_b[v]; argmax over v per b
// Tile: 64(b) x 128(v), BK=16, thread tile 4b x 8v
__global__ void logits_argmax(const float* __restrict__ outW,
                              const float* __restrict__ outb,
                              int hp)   // parity of h buffer to read
{
    __shared__ float Hs[16][65];
    __shared__ float Ws[16][132];
    __shared__ unsigned long long red[64][17];

    const float* h = hbuf(hp);
    const int tid = threadIdx.x;
    const int v0  = blockIdx.x * 128;
    const int tx  = tid & 15;   // v frag (8 each)
    const int ty  = tid >> 4;   // b frag (4 each)

    float acc[4][8];
    #pragma unroll
    for (int i = 0; i < 4; i++)
        #pragma unroll
        for (int j = 0; j < 8; j++) acc[i][j] = 0.f;

    for (int k0 = 0; k0 < H; k0 += 16) {   // 19 iterations (last partial)
        #pragma unroll
        for (int i = 0; i < 4; i++) {
            int idx = tid + i * 256;
            int b = idx >> 4, kk = idx & 15;
            int k = k0 + kk;
            Hs[kk][b] = (k < H) ? h[b * H + k] : 0.f;
        }
        #pragma unroll
        for (int i = 0; i < 8; i++) {
            int idx = tid + i * 256;
            int kk = idx & 15, n = idx >> 4;
            int gv = v0 + n, k = k0 + kk;
            Ws[kk][n] = (gv < V && k < H) ? outW[gv * H + k] : 0.f;
        }
        __syncthreads();
        #pragma unroll
        for (int kk = 0; kk < 16; kk++) {
            float a[4];
            #pragma unroll
            for (int i = 0; i < 4; i++) a[i] = Hs[kk][ty * 4 + i];
            float4 w0 = *(const float4*)&Ws[kk][tx * 8];
            float4 w1 = *(const float4*)&Ws[kk][tx * 8 + 4];
            float w[8] = {w0.x, w0.y, w0.z, w0.w, w1.x, w1.y, w1.z, w1.w};
            #pragma unroll
            for (int i = 0; i < 4; i++)
                #pragma unroll
                for (int j = 0; j < 8; j++)
                    acc[i][j] += a[i] * w[j];
        }
        __syncthreads();
    }

    // epilogue: bias + packed argmax (monotone-float key | ~idx so ties pick lowest idx)
    unsigned long long best[4] = {0ULL, 0ULL, 0ULL, 0ULL};
    #pragma unroll
    for (int j = 0; j < 8; j++) {
        int gv = v0 + tx * 8 + j;
        if (gv >= V) continue;
        float bb = outb[gv];
        #pragma unroll
        for (int i = 0; i < 4; i++) {
            float logit = acc[i][j] + bb;
            unsigned u = __float_as_uint(logit);
            u = (u & 0x80000000u) ? ~u : (u | 0x80000000u);
            unsigned long long pk =
                ((unsigned long long)u << 32) | (unsigned long long)(0xFFFFFFFFu - (unsigned)gv);
            if (pk > best[i]) best[i] = pk;
        }
    }
    #pragma unroll
    for (int i = 0; i < 4; i++) red[ty * 4 + i][tx] = best[i];
    __syncthreads();
    if (tid < 64) {
        unsigned long long m = 0ULL;
        #pragma unroll
        for (int t2 = 0; t2 < 16; t2++) {
            unsigned long long q = red[tid][t2];
            if (q > m) m = q;
        }
        atomicMax(&d_amax[tid], m);
    }
}

// ---------------- finalize: extract ids, write output, reset ----------------
__global__ void finalize_kernel(float* __restrict__ out, int t) {
    int b = threadIdx.x;
    if (b < B) {
        unsigned long long p = d_amax[b];
        int idx = (int)(0xFFFFFFFFu - (unsigned)(p & 0xFFFFFFFFULL));
        d_ids[b] = idx;
        out[t * B + b] = (float)idx;
        d_amax[b] = 0ULL;
    }
}

// ---------------- launch ----------------
extern "C" void kernel_launch(void* const* d_in, const int* in_sizes, int n_in,
                              void* d_out, int out_size)
{
    const int*   input = (const int*)  d_in[0];
    const float* emb   = (const float*)d_in[1];
    const float* eWih  = (const float*)d_in[2];
    const float* eWhh  = (const float*)d_in[3];
    const float* ebih  = (const float*)d_in[4];
    const float* ebhh  = (const float*)d_in[5];
    const float* dWih  = (const float*)d_in[6];
    const float* dWhh  = (const float*)d_in[7];
    const float* dbih  = (const float*)d_in[8];
    const float* dbhh  = (const float*)d_in[9];
    const float* outW  = (const float*)d_in[10];
    const float* outb  = (const float*)d_in[11];
    float* out = (float*)d_out;

    init_kernel<<<(B * H + 255) / 256, 256>>>();

    dim3 gemm_grid((G3 + 15) / 16, 1, 2);   // 57 x 1 x 2

    // ---- encoder ----
    for (int t = 0; t < LL; t++) {
        int p = t & 1;
        gru_gemm<<<gemm_grid, 256>>>(emb, input + t * B, 0, eWih, eWhh, p);
        gru_combine<<<(B * H + 255) / 256, 256>>>(ebih, ebhh, p);
    }
    // ---- decoder ----
    for (int t = 0; t < LL; t++) {
        int p = t & 1;
        gru_gemm<<<gemm_grid, 256>>>(emb, nullptr, 1, dWih, dWhh, p);
        gru_combine<<<(B * H + 255) / 256, 256>>>(dbih, dbhh, p);
        logits_argmax<<<(V + 127) / 128, 256>>>(outW, outb, p ^ 1);
        finalize_kernel<<<1, 64>>>(out, t);
    }
}

// round 3
// speedup vs baseline: 1.8012x; 1.8012x over previous
#include <cuda_runtime.h>
#include <cuda_fp16.h>

#define V   100000
#define H   300
#define LL  64
#define B   64
#define G3  900
#define KP  320            // padded K for logits (20 x 16)
#define NCHUNK 20
#define HS  328            // smem stride (halfs) for h tiles
#define WST 24             // smem stride (halfs) for W tiles
#define NTILE 256
#define NBLK ((V + NTILE - 1) / NTILE)   // 391

// ---------------- device state ----------------
__device__ float d_h0[B * H];
__device__ float d_h1[B * H];
__device__ float d_gi[B * G3];
__device__ float d_gh[B * G3];
__device__ float d_gi_all[LL * B * G3];
__device__ float d_Wt[4][300 * 1024];          // transposed padded GRU weights
__device__ __half d_Whi[(size_t)V * KP];       // chunked [20][V][16]
__device__ __half d_Wlo[(size_t)V * KP];
__device__ __half d_hhi[B * KP];
__device__ __half d_hlo[B * KP];
__device__ int    d_ids[B];
__device__ unsigned long long d_amax[B];

__device__ __forceinline__ unsigned long long umax64(unsigned long long a, unsigned long long b) {
    return a > b ? a : b;
}
__device__ __forceinline__ unsigned long long pack_key(float x, int v) {
    unsigned u = __float_as_uint(x);
    u = (u & 0x80000000u) ? ~u : (u | 0x80000000u);
    return ((unsigned long long)u << 32) | (unsigned long long)(0xFFFFFFFFu - (unsigned)v);
}

// ---------------- init ----------------
__global__ void init_k() {
    int i = blockIdx.x * 256 + threadIdx.x;
    if (i < B * H) d_h0[i] = 0.f;
    if (i < B * KP) { d_hhi[i] = __float2half(0.f); d_hlo[i] = __float2half(0.f); }
    if (i < B) { d_ids[i] = 0; d_amax[i] = 0ULL; }
}

// ---------------- prep: split out_W into fp16 hi/lo, chunked layout ----------------
__global__ void prep_w(const float* __restrict__ outW) {
    size_t i = (size_t)blockIdx.x * 256 + threadIdx.x;
    if (i >= (size_t)V * KP) return;
    int v = (int)(i / KP), k = (int)(i % KP);
    float w = (k < H) ? outW[(size_t)v * H + k] : 0.f;
    __half hi = __float2half(w);
    float lo = w - __half2float(hi);
    size_t idx = (size_t)(k >> 4) * V * 16 + (size_t)v * 16 + (k & 15);
    d_Whi[idx] = hi;
    d_Wlo[idx] = __float2half(lo);
}

// ---------------- prep: transpose GRU weights to [k][n-padded-1024] ----------------
__global__ void prep_wt(const float* __restrict__ a, const float* __restrict__ b,
                        const float* __restrict__ c, const float* __restrict__ d) {
    int z = blockIdx.y;
    const float* src = (z == 0) ? a : (z == 1) ? b : (z == 2) ? c : d;
    int i = blockIdx.x * 256 + threadIdx.x;
    if (i >= 300 * 1024) return;
    int k = i >> 10, n = i & 1023;
    d_Wt[z][i] = (n < G3) ? src[n * H + k] : 0.f;
}

// ---------------- encoder: gi for ALL timesteps in one GEMM ----------------
__global__ void enc_gi_all(const int* __restrict__ input, const float* __restrict__ emb) {
    __shared__ float xs[4][304];
    __shared__ int ids4[4];
    int row0 = blockIdx.y * 4;
    int tid = threadIdx.x;
    if (tid < 4) {
        int row = row0 + tid;
        ids4[tid] = input[(row >> 6) * B + (row & 63)];
    }
    __syncthreads();
    for (int idx = tid; idx < 4 * H; idx += 256) {
        int r = idx / H, k = idx - r * H;
        xs[r][k] = emb[(size_t)ids4[r] * H + k];
    }
    __syncthreads();
    int slot = tid & 63, bl = tid >> 6;
    int n = blockIdx.x * 256 + slot * 4;
    const float* W = d_Wt[0];
    const float* xr = xs[bl];
    float4 acc = make_float4(0.f, 0.f, 0.f, 0.f);
    for (int k0 = 0; k0 < H; k0 += 4) {
        float4 hx = *(const float4*)(xr + k0);
        const float* wp = W + (size_t)k0 * 1024 + n;
        float4 w0 = *(const float4*)(wp);
        float4 w1 = *(const float4*)(wp + 1024);
        float4 w2 = *(const float4*)(wp + 2048);
        float4 w3 = *(const float4*)(wp + 3072);
        acc.x += hx.x * w0.x + hx.y * w1.x + hx.z * w2.x + hx.w * w3.x;
        acc.y += hx.x * w0.y + hx.y * w1.y + hx.z * w2.y + hx.w * w3.y;
        acc.z += hx.x * w0.z + hx.y * w1.z + hx.z * w2.z + hx.w * w3.z;
        acc.w += hx.x * w0.w + hx.y * w1.w + hx.z * w2.w + hx.w * w3.w;
    }
    if (n < G3) *(float4*)&d_gi_all[(size_t)(row0 + bl) * G3 + n] = acc;
}

// ---------------- per-step encoder gh = h @ W_hh^T ----------------
__global__ void enc_gh(int p) {
    __shared__ float xs[4][304];
    const float* h = p ? d_h1 : d_h0;
    int b0 = blockIdx.y * 4;
    int tid = threadIdx.x;
    for (int idx = tid; idx < 4 * H; idx += 256) {
        int r = idx / H, k = idx - r * H;
        xs[r][k] = h[(b0 + r) * H + k];
    }
    __syncthreads();
    int slot = tid & 63, bl = tid >> 6;
    int n = blockIdx.x * 256 + slot * 4;
    const float* W = d_Wt[1];
    const float* xr = xs[bl];
    float4 acc = make_float4(0.f, 0.f, 0.f, 0.f);
    for (int k0 = 0; k0 < H; k0 += 4) {
        float4 hx = *(const float4*)(xr + k0);
        const float* wp = W + (size_t)k0 * 1024 + n;
        float4 w0 = *(const float4*)(wp);
        float4 w1 = *(const float4*)(wp + 1024);
        float4 w2 = *(const float4*)(wp + 2048);
        float4 w3 = *(const float4*)(wp + 3072);
        acc.x += hx.x * w0.x + hx.y * w1.x + hx.z * w2.x + hx.w * w3.x;
        acc.y += hx.x * w0.y + hx.y * w1.y + hx.z * w2.y + hx.w * w3.y;
        acc.z += hx.x * w0.z + hx.y * w1.z + hx.z * w2.z + hx.w * w3.z;
        acc.w += hx.x * w0.w + hx.y * w1.w + hx.z * w2.w + hx.w * w3.w;
    }
    if (n < G3) *(float4*)&d_gh[(b0 + bl) * G3 + n] = acc;
}

// ---------------- per-step decoder: z=0 gi (relu emb gather), z=1 gh ----------------
__global__ void dec_gemm(const float* __restrict__ emb, int p) {
    __shared__ float xs[4][304];
    __shared__ int ids4[4];
    int z = blockIdx.z;
    int b0 = blockIdx.y * 4;
    int tid = threadIdx.x;
    if (z == 0) {
        if (tid < 4) ids4[tid] = d_ids[b0 + tid];
        __syncthreads();
        for (int idx = tid; idx < 4 * H; idx += 256) {
            int r = idx / H, k = idx - r * H;
            xs[r][k] = fmaxf(emb[(size_t)ids4[r] * H + k], 0.f);
        }
    } else {
        const float* h = p ? d_h1 : d_h0;
        for (int idx = tid; idx < 4 * H; idx += 256) {
            int r = idx / H, k = idx - r * H;
            xs[r][k] = h[(b0 + r) * H + k];
        }
    }
    __syncthreads();
    int slot = tid & 63, bl = tid >> 6;
    int n = blockIdx.x * 256 + slot * 4;
    const float* W = d_Wt[z == 0 ? 2 : 3];
    const float* xr = xs[bl];
    float4 acc = make_float4(0.f, 0.f, 0.f, 0.f);
    for (int k0 = 0; k0 < H; k0 += 4) {
        float4 hx = *(const float4*)(xr + k0);
        const float* wp = W + (size_t)k0 * 1024 + n;
        float4 w0 = *(const float4*)(wp);
        float4 w1 = *(const float4*)(wp + 1024);
        float4 w2 = *(const float4*)(wp + 2048);
        float4 w3 = *(const float4*)(wp + 3072);
        acc.x += hx.x * w0.x + hx.y * w1.x + hx.z * w2.x + hx.w * w3.x;
        acc.y += hx.x * w0.y + hx.y * w1.y + hx.z * w2.y + hx.w * w3.y;
        acc.z += hx.x * w0.z + hx.y * w1.z + hx.z * w2.z + hx.w * w3.z;
        acc.w += hx.x * w0.w + hx.y * w1.w + hx.z * w2.w + hx.w * w3.w;
    }
    float* out = z ? d_gh : d_gi;
    if (n < G3) *(float4*)&out[(b0 + bl) * G3 + n] = acc;
}

// ---------------- GRU combine (+ optional fp16 hi/lo split of new h) ----------------
__global__ void combine_k(int use_all, int t, const float* __restrict__ bih,
                          const float* __restrict__ bhh, int p, int split) {
    int i = blockIdx.x * 256 + threadIdx.x;
    if (i >= B * H) return;
    int b = i / H, k = i - b * H;
    const float* h_in = p ? d_h1 : d_h0;
    float* h_out = p ? d_h0 : d_h1;
    const float* gib = (use_all ? d_gi_all + (size_t)t * B * G3 : d_gi) + b * G3;
    const float* ghb = d_gh + b * G3;

    float sr  = gib[k]         + bih[k]         + ghb[k]         + bhh[k];
    float sz  = gib[H + k]     + bih[H + k]     + ghb[H + k]     + bhh[H + k];
    float in_ = gib[2 * H + k] + bih[2 * H + k];
    float hn  = ghb[2 * H + k] + bhh[2 * H + k];

    float r = 1.f / (1.f + expf(-sr));
    float z = 1.f / (1.f + expf(-sz));
    float nn = tanhf(in_ + r * hn);
    float hv = (1.f - z) * nn + z * h_in[i];
    h_out[i] = hv;
    if (split) {
        __half hi = __float2half(hv);
        d_hhi[b * KP + k] = hi;
        d_hlo[b * KP + k] = __float2half(hv - __half2float(hi));
    }
}

// ---------------- logits: fp16 hi/lo tensor-core GEMM + fused argmax ----------------
__device__ __forceinline__ unsigned cvta_s(const void* p) {
    return (unsigned)__cvta_generic_to_shared(p);
}
__device__ __forceinline__ void ldsm_x4(unsigned* r, unsigned a) {
    asm volatile("ldmatrix.sync.aligned.m8n8.x4.shared.b16 {%0,%1,%2,%3}, [%4];"
        : "=r"(r[0]), "=r"(r[1]), "=r"(r[2]), "=r"(r[3]) : "r"(a));
}
__device__ __forceinline__ void mma_16816(float* c, const unsigned* a, const unsigned* b) {
    asm volatile("mma.sync.aligned.m16n8k16.row.col.f32.f16.f16.f32 "
        "{%0,%1,%2,%3}, {%4,%5,%6,%7}, {%8,%9}, {%0,%1,%2,%3};"
        : "+f"(c[0]), "+f"(c[1]), "+f"(c[2]), "+f"(c[3])
        : "r"(a[0]), "r"(a[1]), "r"(a[2]), "r"(a[3]), "r"(b[0]), "r"(b[1]));
}
__device__ __forceinline__ void cp16(unsigned d, const void* s) {
    asm volatile("cp.async.cg.shared.global [%0], [%1], 16;" :: "r"(d), "l"(s));
}

#define WBUF (2 * 256 * WST)   // halfs per double-buffer slot (hi+lo)
#define LOGITS_SMEM (2 * 64 * HS * 2 + 2 * WBUF * 2)   // 83968 + 49152 = 133120 bytes

__device__ __forceinline__ void load_chunk(__half* sW, int c, int buf, int v0, int tid) {
    const __half* ghi = d_Whi + (size_t)c * V * 16;
    const __half* glo = d_Wlo + (size_t)c * V * 16;
    __half* dhi = sW + buf * WBUF;
    __half* dlo = dhi + 256 * WST;
    #pragma unroll
    for (int j = 0; j < 2; j++) {
        int t = tid + j * 256;
        int row = t >> 1, hf = t & 1;
        int v = v0 + row;
        if (v < V) {
            cp16(cvta_s(dhi + row * WST + hf * 8), ghi + (size_t)v * 16 + hf * 8);
            cp16(cvta_s(dlo + row * WST + hf * 8), glo + (size_t)v * 16 + hf * 8);
        }
    }
}

__global__ void __launch_bounds__(256, 1)
logits_k(const float* __restrict__ outb) {
    extern __shared__ __align__(16) char smem[];
    __half* sAhi = (__half*)smem;            // [64][HS]
    __half* sAlo = sAhi + 64 * HS;
    __half* sW   = sAlo + 64 * HS;           // [2 buf][2 mat][256][WST]

    int tid = threadIdx.x;
    int warp = tid >> 5, lane = tid & 31;
    int v0 = blockIdx.x * NTILE;
    int wn = warp * 32;

    // prologue: start chunk 0 stream, then stage h tiles
    load_chunk(sW, 0, 0, v0, tid);
    asm volatile("cp.async.commit_group;" ::: "memory");

    for (int i = tid; i < B * KP / 4; i += 256) {
        int b = i / 80, c = i - b * 80;
        uint2 vhi = ((const uint2*)d_hhi)[i];
        uint2 vlo = ((const uint2*)d_hlo)[i];
        *(uint2*)(sAhi + b * HS + c * 4) = vhi;
        *(uint2*)(sAlo + b * HS + c * 4) = vlo;
    }

    float acc[4][4][4];
    #pragma unroll
    for (int mi = 0; mi < 4; mi++)
        #pragma unroll
        for (int nt = 0; nt < 4; nt++)
            #pragma unroll
            for (int q = 0; q < 4; q++) acc[mi][nt][q] = 0.f;

    int buf = 0;
    for (int c = 0; c < NCHUNK; c++) {
        if (c + 1 < NCHUNK) {
            load_chunk(sW, c + 1, buf ^ 1, v0, tid);
            asm volatile("cp.async.commit_group;" ::: "memory");
            asm volatile("cp.async.wait_group 1;" ::: "memory");
        } else {
            asm volatile("cp.async.wait_group 0;" ::: "memory");
        }
        __syncthreads();

        int k0 = c * 16;
        unsigned ahi[4][4], alo[4][4];
        #pragma unroll
        for (int mi = 0; mi < 4; mi++) {
            int rowA = mi * 16 + (lane & 15);
            int colA = k0 + ((lane >> 4) << 3);
            ldsm_x4(ahi[mi], cvta_s(sAhi + rowA * HS + colA));
            ldsm_x4(alo[mi], cvta_s(sAlo + rowA * HS + colA));
        }
        __half* wb_hi = sW + buf * WBUF;
        __half* wb_lo = wb_hi + 256 * WST;
        unsigned bhi[2][4], blo[2][4];
        #pragma unroll
        for (int pr = 0; pr < 2; pr++) {
            // W smem is [v][k] (k contiguous) == col-major B for row.col mma:
            // load with NON-trans ldmatrix. Groups: (n0-7,k0-7),(n0-7,k8-15),
            // (n8-15,k0-7),(n8-15,k8-15) -> regs r0..r3.
            int rowB = wn + pr * 16 + ((lane & 7) | (((lane >> 4) & 1) << 3));
            int colB = ((lane >> 3) & 1) * 8;
            ldsm_x4(bhi[pr], cvta_s(wb_hi + rowB * WST + colB));
            ldsm_x4(blo[pr], cvta_s(wb_lo + rowB * WST + colB));
        }
        #pragma unroll
        for (int mi = 0; mi < 4; mi++)
            #pragma unroll
            for (int pr = 0; pr < 2; pr++) {
                mma_16816(acc[mi][pr * 2 + 0], ahi[mi], &bhi[pr][0]);
                mma_16816(acc[mi][pr * 2 + 1], ahi[mi], &bhi[pr][2]);
                mma_16816(acc[mi][pr * 2 + 0], ahi[mi], &blo[pr][0]);
                mma_16816(acc[mi][pr * 2 + 1], ahi[mi], &blo[pr][2]);
                mma_16816(acc[mi][pr * 2 + 0], alo[mi], &bhi[pr][0]);
                mma_16816(acc[mi][pr * 2 + 1], alo[mi], &bhi[pr][2]);
            }
        __syncthreads();
        buf ^= 1;
    }

    // ---- epilogue: bias + packed argmax ----
    unsigned long long* red = (unsigned long long*)smem;   // reuse (sA done)
    #pragma unroll
    for (int mi = 0; mi < 4; mi++) {
        unsigned long long k0v = 0ULL, k1v = 0ULL;
        #pragma unroll
        for (int nt = 0; nt < 4; nt++) {
            #pragma unroll
            for (int j = 0; j < 2; j++) {
                int n = v0 + wn + nt * 8 + (lane & 3) * 2 + j;
                if (n < V) {
                    float bias = outb[n];
                    k0v = umax64(k0v, pack_key(acc[mi][nt][j] + bias, n));
                    k1v = umax64(k1v, pack_key(acc[mi][nt][2 + j] + bias, n));
                }
            }
        }
        k0v = umax64(k0v, __shfl_xor_sync(0xffffffffu, k0v, 1));
        k0v = umax64(k0v, __shfl_xor_sync(0xffffffffu, k0v, 2));
        k1v = umax64(k1v, __shfl_xor_sync(0xffffffffu, k1v, 1));
        k1v = umax64(k1v, __shfl_xor_sync(0xffffffffu, k1v, 2));
        if ((lane & 3) == 0) {
            int br = mi * 16 + (lane >> 2);
            red[br * 8 + warp] = k0v;
            red[(br + 8) * 8 + warp] = k1v;
        }
    }
    __syncthreads();
    if (tid < 64) {
        unsigned long long m = 0ULL;
        #pragma unroll
        for (int w = 0; w < 8; w++) m = umax64(m, red[tid * 8 + w]);
        atomicMax(&d_amax[tid], m);
    }
}

// ---------------- finalize ----------------
__global__ void finalize_k(float* __restrict__ out, int t) {
    int b = threadIdx.x;
    if (b < B) {
        unsigned long long p = d_amax[b];
        int idx = (int)(0xFFFFFFFFu - (unsigned)(p & 0xFFFFFFFFULL));
        d_ids[b] = idx;
        out[t * B + b] = (float)idx;
        d_amax[b] = 0ULL;
    }
}

// ---------------- launch ----------------
extern "C" void kernel_launch(void* const* d_in, const int* in_sizes, int n_in,
                              void* d_out, int out_size)
{
    const int*   input = (const int*)  d_in[0];
    const float* emb   = (const float*)d_in[1];
    const float* eWih  = (const float*)d_in[2];
    const float* eWhh  = (const float*)d_in[3];
    const float* ebih  = (const float*)d_in[4];
    const float* ebhh  = (const float*)d_in[5];
    const float* dWih  = (const float*)d_in[6];
    const float* dWhh  = (const float*)d_in[7];
    const float* dbih  = (const float*)d_in[8];
    const float* dbhh  = (const float*)d_in[9];
    const float* outW  = (const float*)d_in[10];
    const float* outb  = (const float*)d_in[11];
    float* out = (float*)d_out;

    cudaFuncSetAttribute(logits_k, cudaFuncAttributeMaxDynamicSharedMemorySize, LOGITS_SMEM);

    init_k<<<(B * KP + 255) / 256, 256>>>();
    prep_w<<<(int)(((size_t)V * KP + 255) / 256), 256>>>(outW);
    prep_wt<<<dim3(1200, 4), 256>>>(eWih, eWhh, dWih, dWhh);
    enc_gi_all<<<dim3(4, 1024), 256>>>(input, emb);

    // ---- encoder ----
    for (int t = 0; t < LL; t++) {
        int p = t & 1;
        enc_gh<<<dim3(4, 16), 256>>>(p);
        combine_k<<<(B * H + 255) / 256, 256>>>(1, t, ebih, ebhh, p, 0);
    }
    // ---- decoder ----
    for (int t = 0; t < LL; t++) {
        int p = t & 1;
        dec_gemm<<<dim3(4, 16, 2), 256>>>(emb, p);
        combine_k<<<(B * H + 255) / 256, 256>>>(0, 0, dbih, dbhh, p, 1);
        logits_k<<<NBLK, 256, LOGITS_SMEM>>>(outb);
        finalize_k<<<1, 64>>>(out, t);
    }
}

// round 7
// speedup vs baseline: 2.4403x; 1.3549x over previous
#include <cuda_runtime.h>
#include <cuda_fp16.h>

#define V      100000
#define VP     100096              // 391 * 256, padded
#define H      300
#define LL     64
#define B      64
#define G3     900
#define KP     320                 // padded K (20 x 16)  -- R3-proven constants
#define NCHUNK 20
#define NTILE  256
#define NBLK   391
#define SA_STR 328                 // halfs; A row stride (R3-proven)
#define WST    24                  // halfs; W row stride (R3-proven)

// pass-1 smem layout (bytes)
#define SA_BYTES (64 * SA_STR * 2)          // 41984
#define SW_OFF   SA_BYTES
#define WBUFB    (256 * WST * 2)            // 12288 per slot
#define P1_SMEM  (SW_OFF + 2 * WBUFB)       // 66560

// ---------------- device state ----------------
__device__ float d_h0[B * H];
__device__ float d_h1[B * H];
__device__ float d_gi[B * G3];
__device__ float d_gh[B * G3];
__device__ float d_gi_all[LL * B * G3];
__device__ float d_Wt[4][300 * 1024];
__device__ __half d_Whi[(size_t)NCHUNK * VP * 16];   // [kc][v][16] chunked
__device__ __half d_hhi[B * KP];
__device__ __half d_alog[(size_t)B * VP];            // approx logits
__device__ int    d_ids[B];

__device__ __forceinline__ unsigned long long umax64(unsigned long long a, unsigned long long b) {
    return a > b ? a : b;
}
__device__ __forceinline__ unsigned mono32(float x) {
    unsigned u = __float_as_uint(x);
    return (u & 0x80000000u) ? ~u : (u | 0x80000000u);
}
__device__ __forceinline__ unsigned long long pack_key(float x, int v) {
    return ((unsigned long long)mono32(x) << 32) |
           (unsigned long long)(0xFFFFFFFFu - (unsigned)v);
}
__device__ __forceinline__ unsigned cvta_s(const void* p) {
    return (unsigned)__cvta_generic_to_shared(p);
}

// ---------------- init ----------------
__global__ void init_k() {
    int i = blockIdx.x * 256 + threadIdx.x;
    if (i < B * H) d_h0[i] = 0.f;
    if (i < B * KP) d_hhi[i] = __float2half(0.f);
    if (i < B) d_ids[i] = 0;
}

// ---------------- prep: out_W -> fp16, chunked [kc][v][16], VP-padded ----------------
__global__ void prep_w(const float* __restrict__ outW) {
    size_t i = (size_t)blockIdx.x * 256 + threadIdx.x;
    if (i >= (size_t)NCHUNK * VP * 16) return;
    int kk = (int)(i & 15);
    size_t r = i >> 4;
    int v = (int)(r % VP);
    int kc = (int)(r / VP);
    int k = kc * 16 + kk;
    float w = (v < V && k < H) ? outW[(size_t)v * H + k] : 0.f;
    d_Whi[i] = __float2half(w);
}

// ---------------- prep: transpose GRU weights to [k][n-padded-1024] ----------------
__global__ void prep_wt(const float* __restrict__ a, const float* __restrict__ b,
                        const float* __restrict__ c, const float* __restrict__ d) {
    int z = blockIdx.y;
    const float* src = (z == 0) ? a : (z == 1) ? b : (z == 2) ? c : d;
    int i = blockIdx.x * 256 + threadIdx.x;
    if (i >= 300 * 1024) return;
    int k = i >> 10, n = i & 1023;
    d_Wt[z][i] = (n < G3) ? src[n * H + k] : 0.f;
}

// ---------------- encoder: gi for ALL timesteps (16 rows/block) ----------------
__global__ void enc_gi_all(const int* __restrict__ input, const float* __restrict__ emb) {
    __shared__ float xs[16][304];
    __shared__ int ids16[16];
    int row0 = blockIdx.y * 16;
    int tid = threadIdx.x;
    if (tid < 16) {
        int row = row0 + tid;
        ids16[tid] = input[(row >> 6) * B + (row & 63)];
    }
    __syncthreads();
    for (int idx = tid; idx < 16 * H; idx += 256) {
        int r = idx / H, k = idx - r * H;
        xs[r][k] = emb[(size_t)ids16[r] * H + k];
    }
    __syncthreads();
    int slot = tid & 63, rg = tid >> 6;
    int n = blockIdx.x * 256 + slot * 4;
    const float* W = d_Wt[0];
    float4 acc[4];
    #pragma unroll
    for (int r = 0; r < 4; r++) acc[r] = make_float4(0.f, 0.f, 0.f, 0.f);
    for (int k0 = 0; k0 < H; k0 += 4) {
        const float* wp = W + (size_t)k0 * 1024 + n;
        float4 w0 = *(const float4*)(wp);
        float4 w1 = *(const float4*)(wp + 1024);
        float4 w2 = *(const float4*)(wp + 2048);
        float4 w3 = *(const float4*)(wp + 3072);
        #pragma unroll
        for (int r = 0; r < 4; r++) {
            float4 hx = *(const float4*)&xs[rg * 4 + r][k0];
            acc[r].x += hx.x * w0.x + hx.y * w1.x + hx.z * w2.x + hx.w * w3.x;
            acc[r].y += hx.x * w0.y + hx.y * w1.y + hx.z * w2.y + hx.w * w3.y;
            acc[r].z += hx.x * w0.z + hx.y * w1.z + hx.z * w2.z + hx.w * w3.z;
            acc[r].w += hx.x * w0.w + hx.y * w1.w + hx.z * w2.w + hx.w * w3.w;
        }
    }
    if (n < G3) {
        #pragma unroll
        for (int r = 0; r < 4; r++)
            *(float4*)&d_gi_all[(size_t)(row0 + rg * 4 + r) * G3 + n] = acc[r];
    }
}

// ---------------- per-step encoder gh ----------------
__global__ void enc_gh(int p) {
    __shared__ float xs[4][304];
    const float* h = p ? d_h1 : d_h0;
    int b0 = blockIdx.y * 4;
    int tid = threadIdx.x;
    for (int idx = tid; idx < 4 * H; idx += 256) {
        int r = idx / H, k = idx - r * H;
        xs[r][k] = h[(b0 + r) * H + k];
    }
    __syncthreads();
    int slot = tid & 63, bl = tid >> 6;
    int n = blockIdx.x * 256 + slot * 4;
    const float* W = d_Wt[1];
    const float* xr = xs[bl];
    float4 acc = make_float4(0.f, 0.f, 0.f, 0.f);
    for (int k0 = 0; k0 < H; k0 += 4) {
        float4 hx = *(const float4*)(xr + k0);
        const float* wp = W + (size_t)k0 * 1024 + n;
        float4 w0 = *(const float4*)(wp);
        float4 w1 = *(const float4*)(wp + 1024);
        float4 w2 = *(const float4*)(wp + 2048);
        float4 w3 = *(const float4*)(wp + 3072);
        acc.x += hx.x * w0.x + hx.y * w1.x + hx.z * w2.x + hx.w * w3.x;
        acc.y += hx.x * w0.y + hx.y * w1.y + hx.z * w2.y + hx.w * w3.y;
        acc.z += hx.x * w0.z + hx.y * w1.z + hx.z * w2.z + hx.w * w3.z;
        acc.w += hx.x * w0.w + hx.y * w1.w + hx.z * w2.w + hx.w * w3.w;
    }
    if (n < G3) *(float4*)&d_gh[(b0 + bl) * G3 + n] = acc;
}

// ---------------- per-step decoder GEMMs ----------------
__global__ void dec_gemm(const float* __restrict__ emb, int p) {
    __shared__ float xs[4][304];
    __shared__ int ids4[4];
    int z = blockIdx.z;
    int b0 = blockIdx.y * 4;
    int tid = threadIdx.x;
    if (z == 0) {
        if (tid < 4) ids4[tid] = d_ids[b0 + tid];
        __syncthreads();
        for (int idx = tid; idx < 4 * H; idx += 256) {
            int r = idx / H, k = idx - r * H;
            xs[r][k] = fmaxf(emb[(size_t)ids4[r] * H + k], 0.f);
        }
    } else {
        const float* h = p ? d_h1 : d_h0;
        for (int idx = tid; idx < 4 * H; idx += 256) {
            int r = idx / H, k = idx - r * H;
            xs[r][k] = h[(b0 + r) * H + k];
        }
    }
    __syncthreads();
    int slot = tid & 63, bl = tid >> 6;
    int n = blockIdx.x * 256 + slot * 4;
    const float* W = d_Wt[z == 0 ? 2 : 3];
    const float* xr = xs[bl];
    float4 acc = make_float4(0.f, 0.f, 0.f, 0.f);
    for (int k0 = 0; k0 < H; k0 += 4) {
        float4 hx = *(const float4*)(xr + k0);
        const float* wp = W + (size_t)k0 * 1024 + n;
        float4 w0 = *(const float4*)(wp);
        float4 w1 = *(const float4*)(wp + 1024);
        float4 w2 = *(const float4*)(wp + 2048);
        float4 w3 = *(const float4*)(wp + 3072);
        acc.x += hx.x * w0.x + hx.y * w1.x + hx.z * w2.x + hx.w * w3.x;
        acc.y += hx.x * w0.y + hx.y * w1.y + hx.z * w2.y + hx.w * w3.y;
        acc.z += hx.x * w0.z + hx.y * w1.z + hx.z * w2.z + hx.w * w3.z;
        acc.w += hx.x * w0.w + hx.y * w1.w + hx.z * w2.w + hx.w * w3.w;
    }
    float* out = z ? d_gh : d_gi;
    if (n < G3) *(float4*)&out[(b0 + bl) * G3 + n] = acc;
}

// ---------------- GRU combine (+ optional fp16 round of new h) ----------------
__global__ void combine_k(int use_all, int t, const float* __restrict__ bih,
                          const float* __restrict__ bhh, int p, int split) {
    int i = blockIdx.x * 256 + threadIdx.x;
    if (i >= B * H) return;
    int b = i / H, k = i - b * H;
    const float* h_in = p ? d_h1 : d_h0;
    float* h_out = p ? d_h0 : d_h1;
    const float* gib = (use_all ? d_gi_all + (size_t)t * B * G3 : d_gi) + b * G3;
    const float* ghb = d_gh + b * G3;

    float sr  = gib[k]         + bih[k]         + ghb[k]         + bhh[k];
    float sz  = gib[H + k]     + bih[H + k]     + ghb[H + k]     + bhh[H + k];
    float in_ = gib[2 * H + k] + bih[2 * H + k];
    float hn  = ghb[2 * H + k] + bhh[2 * H + k];

    float r = 1.f / (1.f + expf(-sr));
    float z = 1.f / (1.f + expf(-sz));
    float nn = tanhf(in_ + r * hn);
    float hv = (1.f - z) * nn + z * h_in[i];
    h_out[i] = hv;
    if (split) d_hhi[b * KP + k] = __float2half(hv);
}

// ================= logits pass 1: single fp16 mma (R3-proven layout) =================
__device__ __forceinline__ void ldsm_x4(unsigned* r, unsigned a) {
    asm volatile("ldmatrix.sync.aligned.m8n8.x4.shared.b16 {%0,%1,%2,%3}, [%4];"
        : "=r"(r[0]), "=r"(r[1]), "=r"(r[2]), "=r"(r[3]) : "r"(a));
}
__device__ __forceinline__ void mma_16816(float* c, const unsigned* a, const unsigned* b) {
    asm volatile("mma.sync.aligned.m16n8k16.row.col.f32.f16.f16.f32 "
        "{%0,%1,%2,%3}, {%4,%5,%6,%7}, {%8,%9}, {%0,%1,%2,%3};"
        : "+f"(c[0]), "+f"(c[1]), "+f"(c[2]), "+f"(c[3])
        : "r"(a[0]), "r"(a[1]), "r"(a[2]), "r"(a[3]), "r"(b[0]), "r"(b[1]));
}
__device__ __forceinline__ void cp16(unsigned d, const void* s) {
    asm volatile("cp.async.cg.shared.global [%0], [%1], 16;" :: "r"(d), "l"(s));
}

__device__ __forceinline__ void load_W(unsigned sb, int kc, int slot, int v0, int tid) {
    const __half* g = d_Whi + ((size_t)kc * VP + v0) * 16;
    unsigned dst = sb + SW_OFF + slot * WBUFB;
    #pragma unroll
    for (int r = 0; r < 2; r++) {
        int t = tid + r * 256;
        int row = t >> 1, hf = t & 1;
        cp16(dst + row * (WST * 2) + hf * 16, g + (size_t)row * 16 + hf * 8);
    }
}

__global__ void __launch_bounds__(256, 2)
logits1_k(const float* __restrict__ outb) {
    extern __shared__ __align__(16) char smem[];
    unsigned sb = cvta_s(smem);
    __half* sA = (__half*)smem;
    int tid = threadIdx.x, warp = tid >> 5, lane = tid & 31;
    int v0 = blockIdx.x * NTILE;

    load_W(sb, 0, 0, v0, tid);
    asm volatile("cp.async.commit_group;" ::: "memory");

    // stage A (h fp16) 64 x 320 halfs, row stride SA_STR
    for (int i = tid; i < 64 * (KP / 8); i += 256) {
        int b = i / (KP / 8), q = i - b * (KP / 8);
        uint4 val = ((const uint4*)d_hhi)[(size_t)b * (KP / 8) + q];
        *(uint4*)(sA + b * SA_STR + q * 8) = val;
    }

    float acc[4][4][4];
    #pragma unroll
    for (int mi = 0; mi < 4; mi++)
        #pragma unroll
        for (int nt = 0; nt < 4; nt++)
            #pragma unroll
            for (int q = 0; q < 4; q++) acc[mi][nt][q] = 0.f;

    int buf = 0;
    for (int c = 0; c < NCHUNK; c++) {
        if (c + 1 < NCHUNK) {
            load_W(sb, c + 1, buf ^ 1, v0, tid);
            asm volatile("cp.async.commit_group;" ::: "memory");
            asm volatile("cp.async.wait_group 1;" ::: "memory");
        } else {
            asm volatile("cp.async.wait_group 0;" ::: "memory");
        }
        __syncthreads();

        int k0 = c * 16;
        unsigned a[4][4];
        #pragma unroll
        for (int mi = 0; mi < 4; mi++) {
            int rowA = mi * 16 + (lane & 15);
            int colA = k0 + ((lane >> 4) << 3);
            ldsm_x4(a[mi], sb + (rowA * SA_STR + colA) * 2);
        }
        unsigned wbase = sb + SW_OFF + buf * WBUFB;
        unsigned bf[2][4];
        #pragma unroll
        for (int pr = 0; pr < 2; pr++) {
            int rowB = warp * 32 + pr * 16 + ((lane & 7) | (((lane >> 4) & 1) << 3));
            int colB = ((lane >> 3) & 1) * 8;
            ldsm_x4(bf[pr], wbase + (rowB * WST + colB) * 2);
        }
        #pragma unroll
        for (int mi = 0; mi < 4; mi++)
            #pragma unroll
            for (int pr = 0; pr < 2; pr++) {
                mma_16816(acc[mi][pr * 2 + 0], a[mi], &bf[pr][0]);
                mma_16816(acc[mi][pr * 2 + 1], a[mi], &bf[pr][2]);
            }
        __syncthreads();
        buf ^= 1;
    }

    // ---- epilogue: bias + plain fp16 stores of approx logits ----
    int wn = warp * 32;
    #pragma unroll
    for (int nt = 0; nt < 4; nt++) {
        int v = v0 + wn + nt * 8 + (lane & 3) * 2;
        float bias0 = (v < V)     ? outb[v]     : -1e4f;
        float bias1 = (v + 1 < V) ? outb[v + 1] : -1e4f;
        #pragma unroll
        for (int mi = 0; mi < 4; mi++) {
            int r1 = mi * 16 + (lane >> 2);
            int r2 = r1 + 8;
            float f00 = acc[mi][nt][0] + bias0, f01 = acc[mi][nt][1] + bias1;
            float f10 = acc[mi][nt][2] + bias0, f11 = acc[mi][nt][3] + bias1;
            *(__half2*)(d_alog + (size_t)r1 * VP + v) = __floats2half2_rn(f00, f01);
            *(__half2*)(d_alog + (size_t)r2 * VP + v) = __floats2half2_rn(f10, f11);
        }
    }
}

// ================= logits pass 2: one block per batch row =================
// phase A: max over stored approx logits; phase B: exact rescore of candidates.
__global__ void __launch_bounds__(512, 2)
scan_k(const float* __restrict__ outW, const float* __restrict__ outb,
       float* __restrict__ out, int t, int p) {
    __shared__ float smaxs[16];
    __shared__ unsigned long long sbest[16];
    __shared__ float hs[304];
    __shared__ float thr;
    int b = blockIdx.x;
    int tid = threadIdx.x, lane = tid & 31, warp = tid >> 5;
    const __half* arow = d_alog + (size_t)b * VP;
    const float* hrow = (p ? d_h0 : d_h1) + b * H;

    if (tid < H) hs[tid] = hrow[tid];

    // phase A: block max of stored fp16 approx logits
    float mx = -3e38f;
    for (int i = tid; i < VP / 8; i += 512) {
        uint4 pk = ((const uint4*)arow)[i];
        __half hv[8];
        *(uint4*)hv = pk;
        #pragma unroll
        for (int j = 0; j < 8; j++) mx = fmaxf(mx, __half2float(hv[j]));
    }
    #pragma unroll
    for (int o = 16; o; o >>= 1) mx = fmaxf(mx, __shfl_xor_sync(0xffffffffu, mx, o));
    if (lane == 0) smaxs[warp] = mx;
    __syncthreads();
    if (tid == 0) {
        float m2 = smaxs[0];
        #pragma unroll
        for (int w = 1; w < 16; w++) m2 = fmaxf(m2, smaxs[w]);
        thr = m2 - 0.09f;
    }
    __syncthreads();
    float th = thr;

    // phase B: candidates + exact fp32 rescore
    unsigned long long best = 0ULL;
    for (int i = tid; i < VP / 8; i += 512) {
        uint4 pk = ((const uint4*)arow)[i];
        __half hv[8];
        *(uint4*)hv = pk;
        #pragma unroll
        for (int j = 0; j < 8; j++) {
            float f = __half2float(hv[j]);
            int v = i * 8 + j;
            if (f >= th && v < V) {
                float s = outb[v];
                const float* wr = outW + (size_t)v * H;
                for (int k = 0; k < H; k += 4) {
                    float4 w4 = *(const float4*)(wr + k);
                    s += hs[k] * w4.x + hs[k + 1] * w4.y + hs[k + 2] * w4.z + hs[k + 3] * w4.w;
                }
                best = umax64(best, pack_key(s, v));
            }
        }
    }
    #pragma unroll
    for (int o = 16; o; o >>= 1) best = umax64(best, __shfl_xor_sync(0xffffffffu, best, o));
    if (lane == 0) sbest[warp] = best;
    __syncthreads();
    if (tid == 0) {
        unsigned long long m = sbest[0];
        #pragma unroll
        for (int w = 1; w < 16; w++) m = umax64(m, sbest[w]);
        int idx = (int)(0xFFFFFFFFu - (unsigned)(m & 0xFFFFFFFFULL));
        d_ids[b] = idx;
        out[t * B + b] = (float)idx;
    }
}

// ---------------- launch ----------------
extern "C" void kernel_launch(void* const* d_in, const int* in_sizes, int n_in,
                              void* d_out, int out_size)
{
    const int*   input = (const int*)  d_in[0];
    const float* emb   = (const float*)d_in[1];
    const float* eWih  = (const float*)d_in[2];
    const float* eWhh  = (const float*)d_in[3];
    const float* ebih  = (const float*)d_in[4];
    const float* ebhh  = (const float*)d_in[5];
    const float* dWih  = (const float*)d_in[6];
    const float* dWhh  = (const float*)d_in[7];
    const float* dbih  = (const float*)d_in[8];
    const float* dbhh  = (const float*)d_in[9];
    const float* outW  = (const float*)d_in[10];
    const float* outb  = (const float*)d_in[11];
    float* out = (float*)d_out;

    cudaFuncSetAttribute(logits1_k, cudaFuncAttributeMaxDynamicSharedMemorySize, P1_SMEM);

    init_k<<<(B * KP + 255) / 256, 256>>>();
    {
        size_t tot = (size_t)NCHUNK * VP * 16;
        prep_w<<<(int)((tot + 255) / 256), 256>>>(outW);
    }
    prep_wt<<<dim3(1200, 4), 256>>>(eWih, eWhh, dWih, dWhh);
    enc_gi_all<<<dim3(4, 256), 256>>>(input, emb);

    // ---- encoder ----
    for (int t = 0; t < LL; t++) {
        int p = t & 1;
        enc_gh<<<dim3(4, 16), 256>>>(p);
        combine_k<<<(B * H + 255) / 256, 256>>>(1, t, ebih, ebhh, p, 0);
    }
    // ---- decoder ----
    for (int t = 0; t < LL; t++) {
        int p = t & 1;
        dec_gemm<<<dim3(4, 16, 2), 256>>>(emb, p);
        combine_k<<<(B * H + 255) / 256, 256>>>(0, 0, dbih, dbhh, p, 1);
        logits1_k<<<NBLK, 256, P1_SMEM>>>(outb);
        scan_k<<<B, 512>>>(outW, outb, out, t, p);
    }
}